// round 6
// baseline (speedup 1.0000x reference)
#include <cuda_runtime.h>
#include <float.h>

// Problem shape (fixed by the reference)
#define NB 32
#define NT 2048
#define ND 512

#define NC 8                  // chunks (blocks) per batch -> grid (32,8)=256
#define NW 16                 // warps per block (512 threads)
#define ROWS (NT / NC)        // 256 rows per block
#define RPW (ROWS / NW)       // 16 rows per warp

// Scratch (no cudaMalloc allowed)
__device__ __align__(16) float g_s_part[NB * NC * ND];           // 512 KB
__device__ float g_pm[NB * NC];
__device__ float g_pl[NB * NC];
__device__ __align__(16) float g_pacc[(size_t)NB * NC * ND];     // 512 KB
__device__ int g_cnt_s[NB];   // zero-init; reset by last block each launch
__device__ int g_cnt_p[NB];

__device__ __forceinline__ void f4add(float4& a, const float4 b) {
    a.x += b.x; a.y += b.y; a.z += b.z; a.w += b.w;
}

// ---------------------------------------------------------------------------
// Fully fused. Phase 2 is split into independent stages to kill serial deps:
//   2a: per-warp row scores w[t] with BATCHED butterfly reductions (8 rows'
//       shuffles in flight simultaneously) -> sm_w
//   block softmax: M (commutative max), p[t]=exp(w-M) in parallel, L by one
//       fixed-topology warp-0 reduction
//   2b: re-read rows (L2-hot) with register float4 accumulators, zero
//       cross-iteration dependencies; 4 row-groups x 4 col-warps
// All reduction orders fixed -> deterministic.
// ---------------------------------------------------------------------------
__global__ void __launch_bounds__(512, 2)
k_fused(const float* __restrict__ x, float* __restrict__ out) {
    const int b = blockIdx.x, c = blockIdx.y;
    const int tid = threadIdx.x, w = tid >> 5, lane = tid & 31;

    __shared__ float sm_m[NW];
    __shared__ float sm_L;
    __shared__ int sm_last;
    __shared__ __align__(16) float sm_s[ND];          // 2 KB
    __shared__ float sm_w[ROWS];                      // 1 KB
    __shared__ float sm_p[ROWS];                      // 1 KB
    __shared__ __align__(16) float sm_acc[NW][ND];    // 32 KB (reused in 2b)

    const float4* xb = (const float4*)(x + (size_t)b * NT * ND);
    const int tbase = c * ROWS + w;                   // 2a rows: tbase + j*NW

    // ---- Phase 1: column-sum of this block's 256 rows (ascending) ----
    float4 q0 = {0.f, 0.f, 0.f, 0.f}, q1 = q0, q2 = q0, q3 = q0;
    #pragma unroll 2
    for (int j = 0; j < RPW; ++j) {
        const float4* row = xb + (size_t)(tbase + j * NW) * (ND / 4);
        const float4 v0 = row[lane],      v1 = row[32 + lane];
        const float4 v2 = row[64 + lane], v3 = row[96 + lane];
        f4add(q0, v0); f4add(q1, v1); f4add(q2, v2); f4add(q3, v3);
    }
    {
        float4* sa = (float4*)sm_acc[w];
        sa[lane] = q0; sa[32 + lane] = q1; sa[64 + lane] = q2; sa[96 + lane] = q3;
    }
    __syncthreads();
    if (tid < ND / 4) {
        float4 s = {0.f, 0.f, 0.f, 0.f};
        #pragma unroll
        for (int p = 0; p < NW; ++p) f4add(s, ((const float4*)sm_acc[p])[tid]);
        ((float4*)(g_s_part + (size_t)(b * NC + c) * ND))[tid] = s;
    }
    __threadfence();
    __syncthreads();

    // ---- Per-batch inter-block barrier (all 256 blocks co-resident) ----
    if (tid == 0) {
        atomicAdd(&g_cnt_s[b], 1);
        while (atomicAdd(&g_cnt_s[b], 0) < NC) __nanosleep(128);
    }
    __syncthreads();
    __threadfence();

    // ---- Fold the 8 s-partials (fixed order) -> sm_s ----
    if (tid < ND / 4) {
        const float4* sp = (const float4*)(g_s_part + (size_t)b * NC * ND);
        float4 s = {0.f, 0.f, 0.f, 0.f};
        #pragma unroll
        for (int p = 0; p < NC; ++p) f4add(s, sp[p * (ND / 4) + tid]);
        ((float4*)sm_s)[tid] = s;
    }
    __syncthreads();
    const float4* sS = (const float4*)sm_s;

    // ---- Phase 2a: row scores, two batches of 8 rows (descending: L2) ----
    float m = -FLT_MAX;
    #pragma unroll
    for (int half = 1; half >= 0; --half) {
        float r[8];
        #pragma unroll
        for (int k = 0; k < 8; ++k) {
            const int j = half * 8 + (7 - k);           // 15..8 then 7..0
            const float4* row = xb + (size_t)(tbase + j * NW) * (ND / 4);
            const float4 v0 = row[lane];
            const float4 v1 = row[32 + lane];
            const float4 v2 = row[64 + lane];
            const float4 v3 = row[96 + lane];
            const float4 s0 = sS[lane];
            const float4 s1 = sS[32 + lane];
            const float4 s2 = sS[64 + lane];
            const float4 s3 = sS[96 + lane];
            float ra, rb;
            ra = v0.x * (s0.x - v0.x);          rb = v0.y * (s0.y - v0.y);
            ra = fmaf(v0.z, s0.z - v0.z, ra);   rb = fmaf(v0.w, s0.w - v0.w, rb);
            ra = fmaf(v1.x, s1.x - v1.x, ra);   rb = fmaf(v1.y, s1.y - v1.y, rb);
            ra = fmaf(v1.z, s1.z - v1.z, ra);   rb = fmaf(v1.w, s1.w - v1.w, rb);
            ra = fmaf(v2.x, s2.x - v2.x, ra);   rb = fmaf(v2.y, s2.y - v2.y, rb);
            ra = fmaf(v2.z, s2.z - v2.z, ra);   rb = fmaf(v2.w, s2.w - v2.w, rb);
            ra = fmaf(v3.x, s3.x - v3.x, ra);   rb = fmaf(v3.y, s3.y - v3.y, rb);
            ra = fmaf(v3.z, s3.z - v3.z, ra);   rb = fmaf(v3.w, s3.w - v3.w, rb);
            r[k] = ra + rb;
        }
        // batched butterfly: 8 independent reductions in flight
        #pragma unroll
        for (int o = 16; o; o >>= 1) {
            #pragma unroll
            for (int k = 0; k < 8; ++k)
                r[k] += __shfl_xor_sync(0xffffffffu, r[k], o);
        }
        #pragma unroll
        for (int k = 0; k < 8; ++k) {
            m = fmaxf(m, r[k]);
            const int j = half * 8 + (7 - k);
            if (lane == 0) sm_w[w + j * NW] = r[k];     // local row = w + j*16
        }
    }
    if (lane == 0) sm_m[w] = m;
    __syncthreads();

    // ---- Block softmax: M, p[t], L ----
    float M = sm_m[0];
    #pragma unroll
    for (int p = 1; p < NW; ++p) M = fmaxf(M, sm_m[p]);
    if (tid < ROWS) sm_p[tid] = __expf(sm_w[tid] - M);
    __syncthreads();
    if (w == 0) {                       // fixed-topology L reduction
        float a = 0.f;
        #pragma unroll
        for (int i = 0; i < ROWS / 32; ++i) a += sm_p[lane * (ROWS / 32) + i];
        #pragma unroll
        for (int o = 16; o; o >>= 1) a += __shfl_xor_sync(0xffffffffu, a, o);
        if (lane == 0) sm_L = a;
    }

    // ---- Phase 2b: accumulate with register accumulators (L2-hot) ----
    const int g = w >> 2;               // row group 0..3 (64 rows each)
    const int colq = (w & 3) * 32 + lane;   // float4 column index 0..127
    float4 acc = {0.f, 0.f, 0.f, 0.f};
    const int t0 = g * 64;
    #pragma unroll 4
    for (int t = t0; t < t0 + 64; ++t) {
        const float pt = sm_p[t];
        const float4 v = xb[(size_t)(c * ROWS + t) * (ND / 4) + colq];
        acc.x = fmaf(pt, v.x, acc.x); acc.y = fmaf(pt, v.y, acc.y);
        acc.z = fmaf(pt, v.z, acc.z); acc.w = fmaf(pt, v.w, acc.w);
    }
    ((float4*)sm_acc[g])[colq] = acc;   // groups write disjoint sm_acc rows 0..3
    __syncthreads();

    // ---- Fold 4 groups (fixed order) -> block partial ----
    const int pi = b * NC + c;
    if (tid < ND / 4) {
        float4 o = ((const float4*)sm_acc[0])[tid];
        #pragma unroll
        for (int p = 1; p < 4; ++p) f4add(o, ((const float4*)sm_acc[p])[tid]);
        ((float4*)(g_pacc + (size_t)pi * ND))[tid] = o;
    }
    if (tid == 0) { g_pm[pi] = M; g_pl[pi] = sm_L; }
    __threadfence();
    __syncthreads();

    // ---- Last block per batch combines and writes output ----
    if (tid == 0) {
        const int old = atomicAdd(&g_cnt_p[b], 1);
        sm_last = (old == NC - 1);
    }
    __syncthreads();
    if (sm_last) {
        __threadfence();
        if (tid < ND / 4) {
            const float* pm = g_pm + b * NC;
            const float* pl = g_pl + b * NC;
            float MM = -FLT_MAX;
            #pragma unroll
            for (int p = 0; p < NC; ++p) MM = fmaxf(MM, pm[p]);
            float L = 0.f;
            float4 o = {0.f, 0.f, 0.f, 0.f};
            #pragma unroll
            for (int p = 0; p < NC; ++p) {
                const float e = __expf(pm[p] - MM);
                L = fmaf(pl[p], e, L);
                const float4 a =
                    ((const float4*)(g_pacc + (size_t)(b * NC + p) * ND))[tid];
                o.x = fmaf(e, a.x, o.x); o.y = fmaf(e, a.y, o.y);
                o.z = fmaf(e, a.z, o.z); o.w = fmaf(e, a.w, o.w);
            }
            const float inv = 1.f / L;
            o.x *= inv; o.y *= inv; o.z *= inv; o.w *= inv;
            ((float4*)(out + (size_t)b * ND))[tid] = o;
        }
        // reset counters for the next graph replay
        if (tid == 0) {
            atomicExch(&g_cnt_s[b], 0);
            atomicExch(&g_cnt_p[b], 0);
        }
    }
}

// ---------------------------------------------------------------------------
extern "C" void kernel_launch(void* const* d_in, const int* in_sizes, int n_in,
                              void* d_out, int out_size) {
    (void)in_sizes; (void)n_in; (void)out_size;
    const float* x = (const float*)d_in[0];
    float* out = (float*)d_out;

    k_fused<<<dim3(NB, NC), 512>>>(x, out);
}